// round 5
// baseline (speedup 1.0000x reference)
#include <cuda_runtime.h>
#include <cuda_fp16.h>
#include <cstdint>

// PackedViterbi, linear domain, fp16x2 fast path with DAMPED-pivot rescaling.
//   u_t = E_t @ u_{t-1},  E = 2^(theta*log2e) via ex2.approx.f16x2 (2 exps/MUFU
//   issue), dot in HFMA2, u packed f16x2 in SMEM.
// Rescale: c_t with lg2(c_t) = -0.5*lg2(acc0_{t-1}) + BETA  (tid0 only, stale by
// one step, NO extra barrier). Log-scale dynamics x_{t+1} = x_t - 0.5 x_{t-1} + k
// has poles 0.5 +- 0.5i (|z|=0.707) -> exponentially stable, u pinned near 2^-2.
// (The previous full-strength stale pivot had unit-circle poles; the resulting
// undamped oscillation overflowed fp16 -> inf -> NaN.)
// Exact scale offset A accumulated in double by tid0: A -= lg2(c_t) each step.
// E for step t+1 converted during step t; depth-3 LDG prefetch; 6-way rotation.
// One CTA per sequence (64 CTAs), 512 threads: row i = tid>>3, octet oc = tid&7.

static constexpr int S = 64;

__device__ __forceinline__ uint32_t ex2h2_(uint32_t x) {
    uint32_t y; asm("ex2.approx.f16x2 %0, %1;" : "=r"(y) : "r"(x)); return y;
}
__device__ __forceinline__ float lg2_(float x) {
    float y; asm("lg2.approx.f32 %0, %1;" : "=f"(y) : "f"(x)); return y;
}
__device__ __forceinline__ float ex2_(float x) {
    float y; asm("ex2.approx.ftz.f32 %0, %1;" : "=f"(y) : "f"(x)); return y;
}

struct H2x4 { __half2 a, b, c, d; };

__device__ __forceinline__ H2x4 convE(const float4& ra, const float4& rb) {
    const float L2E = 1.4426950408889634f;
    __half2 pa = __floats2half2_rn(ra.x * L2E, ra.y * L2E);
    __half2 pb = __floats2half2_rn(ra.z * L2E, ra.w * L2E);
    __half2 pc = __floats2half2_rn(rb.x * L2E, rb.y * L2E);
    __half2 pd = __floats2half2_rn(rb.z * L2E, rb.w * L2E);
    uint32_t ua = ex2h2_(*reinterpret_cast<uint32_t*>(&pa));
    uint32_t ub = ex2h2_(*reinterpret_cast<uint32_t*>(&pb));
    uint32_t uc = ex2h2_(*reinterpret_cast<uint32_t*>(&pc));
    uint32_t ud = ex2h2_(*reinterpret_cast<uint32_t*>(&pd));
    H2x4 e;
    e.a = *reinterpret_cast<__half2*>(&ua);
    e.b = *reinterpret_cast<__half2*>(&ub);
    e.c = *reinterpret_cast<__half2*>(&uc);
    e.d = *reinterpret_cast<__half2*>(&ud);
    return e;
}

__device__ __forceinline__ float dotE(const H2x4& e, const uint4& uv) {
    __half2 u0 = *reinterpret_cast<const __half2*>(&uv.x);
    __half2 u1 = *reinterpret_cast<const __half2*>(&uv.y);
    __half2 u2 = *reinterpret_cast<const __half2*>(&uv.z);
    __half2 u3 = *reinterpret_cast<const __half2*>(&uv.w);
    __half2 h0 = __hmul2(e.a, u0);
    __half2 h1 = __hmul2(e.b, u1);
    h0 = __hfma2(e.c, u2, h0);
    h1 = __hfma2(e.d, u3, h1);
    h0 = __hadd2(h0, h1);
    return __low2float(h0) + __high2float(h0);
}

__global__ __launch_bounds__(512, 1)
void packed_viterbi_kernel(const float* __restrict__ theta,
                           const int*   __restrict__ lengths,
                           float*       __restrict__ out,
                           int B)
{
    const int b    = blockIdx.x;
    const int tid  = threadIdx.x;
    const int lane = tid & 31;
    const int oc   = tid & 7;          // octet within row: j-range 8*oc..8*oc+7
    const int L    = lengths[b];

    // u packed: slot k holds {u[2k] (lo), u[2k+1] (hi)}
    __shared__ __align__(16) uint32_t u16buf[2][32];
    __shared__ float cbuf[2];

    if (tid < 32) u16buf[0][tid] = 0x3C003C00u;   // {1.0h, 1.0h}
    if (tid == 0) cbuf[0] = 0.015625f;            // 2^-6 (gentle first step)
    __syncthreads();

    const size_t strideF4 = (size_t)B * S * S / 4;      // step stride in float4
    const float4* base4 = reinterpret_cast<const float4*>(
        theta + (size_t)b * S * S + (size_t)(tid >> 3) * S + (size_t)oc * 8);
    const float4* pEnd = base4 + (size_t)(L - 1) * strideF4;

    // prologue: theta for t=0,1,2 (clamped), E for t=0
    float4 r0a, r0b, r1a, r1b, r2a, r2b;
    {
        const float4* q;
        q = base4;                                            r0a = q[0]; r0b = q[1];
        q = base4 + (size_t)((1 < L) ? 1 : L - 1) * strideF4; r1a = q[0]; r1b = q[1];
        q = base4 + (size_t)((2 < L) ? 2 : L - 1) * strideF4; r2a = q[0]; r2b = q[1];
    }
    const float4* pref = base4 + (size_t)((3 < L) ? 3 : L - 1) * strideF4;

    H2x4 e0 = convE(r0a, r0b);
    H2x4 e1;

    const float BETA = -4.36f;     // targets steady-state u ~ 2^-2
    double A = 0.0;                // tid 0 only: true scale offset (lg2 units)
    float  lg2c_cur = -6.0f;       // tid 0 only: lg2 of csc used this step
    const int pairIdx = ((tid >> 5) << 1) + (lane >> 4);  // leader's u16 slot
    int t = 0;

#define VSTEP(ECUR, RNA, RNB, ENEXT, RLA, RLB)                                        \
    {                                                                                 \
        const uint4 uv = *reinterpret_cast<const uint4*>(&u16buf[t & 1][oc << 2]);    \
        const float csc = cbuf[t & 1];                                                \
        RLA = pref[0]; RLB = pref[1];                                                 \
        {   const float4* pn = pref + strideF4;                                       \
            pref = (pn <= pEnd) ? pn : pEnd; }                                        \
        float acc = dotE(ECUR, uv);                                                   \
        acc += __shfl_xor_sync(0xffffffffu, acc, 1);                                  \
        acc += __shfl_xor_sync(0xffffffffu, acc, 2);                                  \
        acc += __shfl_xor_sync(0xffffffffu, acc, 4);                                  \
        const float accs = acc * csc;                                                 \
        const float part = __shfl_xor_sync(0xffffffffu, accs, 8);                     \
        if ((lane & 15) == 0) {                                                       \
            __half2 pk = __floats2half2_rn(accs, part);                               \
            u16buf[(t & 1) ^ 1][pairIdx] = *reinterpret_cast<uint32_t*>(&pk);         \
        }                                                                             \
        if (tid == 0) {                                                               \
            A -= (double)lg2c_cur;                                                    \
            const float m   = lg2_(acc);                                              \
            const float lgc = fmaf(-0.5f, m, BETA);                                   \
            cbuf[(t & 1) ^ 1] = ex2_(lgc);                                            \
            lg2c_cur = lgc;                                                           \
        }                                                                             \
        ENEXT = convE(RNA, RNB);                                                      \
        __syncthreads();                                                              \
    }

    for (;;) {
        VSTEP(e0, r1a, r1b, e1, r0a, r0b); if (++t >= L) break;   // s0
        VSTEP(e1, r2a, r2b, e0, r1a, r1b); if (++t >= L) break;   // s1
        VSTEP(e0, r0a, r0b, e1, r2a, r2b); if (++t >= L) break;   // s2
        VSTEP(e1, r1a, r1b, e0, r0a, r0b); if (++t >= L) break;   // s3
        VSTEP(e0, r2a, r2b, e1, r1a, r1b); if (++t >= L) break;   // s4
        VSTEP(e1, r0a, r0b, e0, r2a, r2b); if (++t >= L) break;   // s5
    }
#undef VSTEP

    if (tid == 0) {
        const uint32_t* w = u16buf[L & 1];
        float s = 0.0f;
        #pragma unroll
        for (int k = 0; k < 32; ++k) {
            __half2 v = *reinterpret_cast<const __half2*>(&w[k]);
            s += __low2float(v) + __high2float(v);
        }
        const double vt = ((double)lg2_(s) + A) * 0.6931471805599453094;
        out[b] = (float)vt;
    }
}

extern "C" void kernel_launch(void* const* d_in, const int* in_sizes, int n_in,
                              void* d_out, int out_size)
{
    const float* theta   = (const float*)d_in[0];
    const int*   lengths = (const int*)d_in[1];
    float*       out     = (float*)d_out;
    const int B = in_sizes[1];   // 64
    packed_viterbi_kernel<<<B, 512>>>(theta, lengths, out, B);
}

// round 6
// speedup vs baseline: 2.0594x; 2.0594x over previous
#include <cuda_runtime.h>
#include <cuda_bf16.h>
#include <cstdint>

// PackedViterbi as a PARALLEL MATRIX-PRODUCT TREE (scan is associative):
//   u_L = E_{L-1} ... E_0 * ones,  E_t = exp(theta_t)  (per sequence b)
//   Vt  = log(sum_i u_L[i])
// Pass A: CTA per (chunk of 8 steps, b): P_c = E_{hi-1}...E_{lo} via 7 chained
//         64x64x64 bf16 HMMA GEMMs (fp32 accum). Leaves: exp2(theta*log2e - 16).
// Pass B: CTA per (group of 8 chunks, b): combine 8 -> 1.
// Pass C: CTA per b: combine up to 8 -> 1, then row-sum + logsum -> out[b].
// After every GEMM: rescale by an EXACT power of 2 (max-entry exponent), offset
// accumulated in fp32 and applied at the end. Inactive steps (t >= L_b) never
// materialized (activity = prefix, handled by loop bounds).

static constexpr int S   = 64;
static constexpr int TT  = 512;
static constexpr int BB  = 64;
static constexpr int LDA = 72;            // padded SMEM stride (bf16 elems)

__device__ __nv_bfloat16 g_buf1[64 * BB * S * S];  // chunk products  (33.5 MB)
__device__ float         g_off1[64 * BB];
__device__ __nv_bfloat16 g_buf2[8 * BB * S * S];   // super-chunk products
__device__ float         g_off2[8 * BB];

__device__ __forceinline__ float ex2f_(float x) {
    float y; asm("ex2.approx.ftz.f32 %0, %1;" : "=f"(y) : "f"(x)); return y;
}

__device__ __forceinline__ void mma16816(float c[4], const uint32_t a[4],
                                         uint32_t b0, uint32_t b1) {
    asm volatile(
        "mma.sync.aligned.m16n8k16.row.col.f32.bf16.bf16.f32 "
        "{%0,%1,%2,%3}, {%4,%5,%6,%7}, {%8,%9}, {%0,%1,%2,%3};\n"
        : "+f"(c[0]), "+f"(c[1]), "+f"(c[2]), "+f"(c[3])
        : "r"(a[0]), "r"(a[1]), "r"(a[2]), "r"(a[3]), "r"(b0), "r"(b1));
}

// ---- SMEM loaders (512 threads, 8 bf16 each) --------------------------------
__device__ __forceinline__ void smem_load_direct(const __nv_bfloat16* __restrict__ g,
                                                 __nv_bfloat16* s) {
    int idx = threadIdx.x * 8;
    int r = idx >> 6, c0 = idx & 63;
    uint4 v = *(const uint4*)(g + idx);
    *(uint4*)(s + r * LDA + c0) = v;
}
__device__ __forceinline__ void smem_load_trans(const __nv_bfloat16* __restrict__ g,
                                                __nv_bfloat16* s) {
    int idx = threadIdx.x * 8;
    int r = idx >> 6, c0 = idx & 63;
    uint4 v = *(const uint4*)(g + idx);
    const __nv_bfloat16* h = (const __nv_bfloat16*)&v;
#pragma unroll
    for (int q = 0; q < 8; ++q) s[(c0 + q) * LDA + r] = h[q];
}
__device__ __forceinline__ void smem_store(const __nv_bfloat16* s,
                                           __nv_bfloat16* __restrict__ g) {
    int idx = threadIdx.x * 8;
    int r = idx >> 6, c0 = idx & 63;
    uint4 v = *(const uint4*)(s + r * LDA + c0);
    *(uint4*)(g + idx) = v;
}
// exp leaf: E = 2^(theta*log2e - 16)  (exact power-of-2 bias, offset 16/leaf)
__device__ __forceinline__ void smem_load_exp(const float* __restrict__ th,
                                              __nv_bfloat16* s, bool trans) {
    const float L2E = 1.4426950408889634f;
    int idx = threadIdx.x * 8;
    int r = idx >> 6, c0 = idx & 63;
    const float4* src = (const float4*)(th + idx);
    float4 v0 = src[0], v1 = src[1];
    float e[8];
    e[0] = ex2f_(fmaf(v0.x, L2E, -16.f)); e[1] = ex2f_(fmaf(v0.y, L2E, -16.f));
    e[2] = ex2f_(fmaf(v0.z, L2E, -16.f)); e[3] = ex2f_(fmaf(v0.w, L2E, -16.f));
    e[4] = ex2f_(fmaf(v1.x, L2E, -16.f)); e[5] = ex2f_(fmaf(v1.y, L2E, -16.f));
    e[6] = ex2f_(fmaf(v1.z, L2E, -16.f)); e[7] = ex2f_(fmaf(v1.w, L2E, -16.f));
    if (!trans) {
        __nv_bfloat16 tmp[8];
#pragma unroll
        for (int q = 0; q < 8; ++q) tmp[q] = __float2bfloat16(e[q]);
        *(uint4*)(s + r * LDA + c0) = *(uint4*)tmp;
    } else {
#pragma unroll
        for (int q = 0; q < 8; ++q) s[(c0 + q) * LDA + r] = __float2bfloat16(e[q]);
    }
}

// ---- CTA GEMM:  Asm <- rescale( Asm(64x64,row) * Btsm(64x64, col-major) ) ---
// 16 warps: warp w -> rows 16*(w>>2).., ntiles 2*(w&3)+{0,1} (8 cols each).
// Returns power-of-2 shift s (result = true / 2^s), same value in all threads.
__device__ __forceinline__ float cta_gemm_rescale(__nv_bfloat16* Asm,
                                                  const __nv_bfloat16* Btsm,
                                                  float* red) {
    const int tid = threadIdx.x;
    const int w = tid >> 5, lane = tid & 31;
    const int g = lane >> 2, t4 = lane & 3;
    const int rb = (w >> 2) * 16;
    const int ng = (w & 3) * 2;

    uint32_t a[4][4];
#pragma unroll
    for (int ks = 0; ks < 4; ++ks) {
        const __nv_bfloat16* base = Asm + (rb + g) * LDA + ks * 16 + t4 * 2;
        a[ks][0] = *(const uint32_t*)(base);
        a[ks][1] = *(const uint32_t*)(base + 8 * LDA);
        a[ks][2] = *(const uint32_t*)(base + 8);
        a[ks][3] = *(const uint32_t*)(base + 8 * LDA + 8);
    }
    float c[2][4];
#pragma unroll
    for (int nt = 0; nt < 2; ++nt) {
        c[nt][0] = c[nt][1] = c[nt][2] = c[nt][3] = 0.f;
        int ncol = (ng + nt) * 8 + g;
#pragma unroll
        for (int ks = 0; ks < 4; ++ks) {
            const __nv_bfloat16* bb = Btsm + ncol * LDA + ks * 16 + t4 * 2;
            uint32_t b0 = *(const uint32_t*)(bb);
            uint32_t b1 = *(const uint32_t*)(bb + 8);
            mma16816(c[nt], a[ks], b0, b1);
        }
    }
    __syncthreads();                       // all reads of Asm/Btsm complete
    float m = 0.f;
#pragma unroll
    for (int nt = 0; nt < 2; ++nt)
#pragma unroll
        for (int q = 0; q < 4; ++q) m = fmaxf(m, c[nt][q]);
#pragma unroll
    for (int off = 16; off; off >>= 1)
        m = fmaxf(m, __shfl_xor_sync(0xffffffffu, m, off));
    if (lane == 0) red[w] = m;
    __syncthreads();
    if (tid == 0) {
        float mm = red[0];
#pragma unroll
        for (int i = 1; i < 16; ++i) mm = fmaxf(mm, red[i]);
        int sft = (int)((__float_as_uint(mm) >> 23) & 0xFF) - 126;   // mm*2^-s in [0.5,1)
        red[16] = __uint_as_float((uint32_t)(127 - sft) << 23);      // exact 2^-s
        red[17] = (float)sft;
    }
    __syncthreads();
    const float scale = red[16];
    const float shift = red[17];
#pragma unroll
    for (int nt = 0; nt < 2; ++nt) {
        int col = (ng + nt) * 8 + t4 * 2;
        __nv_bfloat162 lo = __floats2bfloat162_rn(c[nt][0] * scale, c[nt][1] * scale);
        __nv_bfloat162 hi = __floats2bfloat162_rn(c[nt][2] * scale, c[nt][3] * scale);
        *(uint32_t*)(Asm + (rb + g) * LDA + col)     = *(uint32_t*)&lo;
        *(uint32_t*)(Asm + (rb + g + 8) * LDA + col) = *(uint32_t*)&hi;
    }
    __syncthreads();                       // Asm updated before next use
    return shift;
}

// ---- Pass A: chunks of 8 timesteps ------------------------------------------
__global__ void __launch_bounds__(512, 2)
passA(const float* __restrict__ theta, const int* __restrict__ lengths) {
    __shared__ __nv_bfloat16 Asm[S * LDA];
    __shared__ __nv_bfloat16 Btsm[S * LDA];
    __shared__ float red[18];
    const int c = blockIdx.x, b = blockIdx.y;
    const int L = lengths[b];
    const int t0 = c * 8;
    if (L <= t0) return;
    const int thi = min(L, t0 + 8);
    float off = 16.0f * (float)(thi - t0);
    const size_t mat = (size_t)S * S;

    smem_load_exp(theta + ((size_t)(thi - 1) * BB + b) * mat, Asm, false);
    for (int t = thi - 2; t >= t0; --t) {
        smem_load_exp(theta + ((size_t)t * BB + b) * mat, Btsm, true);
        __syncthreads();
        off += cta_gemm_rescale(Asm, Btsm, red);
    }
    __syncthreads();
    smem_store(Asm, g_buf1 + ((size_t)c * BB + b) * mat);
    if (threadIdx.x == 0) g_off1[c * BB + b] = off;
}

// ---- Pass B: combine 8 chunks -> 1 ------------------------------------------
__global__ void __launch_bounds__(512, 2)
passB(const int* __restrict__ lengths) {
    __shared__ __nv_bfloat16 Asm[S * LDA];
    __shared__ __nv_bfloat16 Btsm[S * LDA];
    __shared__ float red[18];
    const int cc = blockIdx.x, b = blockIdx.y;
    const int L = lengths[b];
    const int totalChunks = (L + 7) >> 3;             // ceil(L/8)
    const int nch = min(totalChunks - cc * 8, 8);
    if (nch <= 0) return;
    const int cb = cc * 8;
    const size_t mat = (size_t)S * S;

    float off = g_off1[(cb + nch - 1) * BB + b];
    smem_load_direct(g_buf1 + ((size_t)(cb + nch - 1) * BB + b) * mat, Asm);
    for (int k = nch - 2; k >= 0; --k) {
        smem_load_trans(g_buf1 + ((size_t)(cb + k) * BB + b) * mat, Btsm);
        off += g_off1[(cb + k) * BB + b];
        __syncthreads();
        off += cta_gemm_rescale(Asm, Btsm, red);
    }
    __syncthreads();
    smem_store(Asm, g_buf2 + ((size_t)cc * BB + b) * mat);
    if (threadIdx.x == 0) g_off2[cc * BB + b] = off;
}

// ---- Pass C: combine up to 8 super-chunks, row-sum, logsum ------------------
__global__ void __launch_bounds__(512, 1)
passC(const int* __restrict__ lengths, float* __restrict__ out) {
    __shared__ __nv_bfloat16 Asm[S * LDA];
    __shared__ __nv_bfloat16 Btsm[S * LDA];
    __shared__ float red[18];
    const int b = blockIdx.x;
    const int L = lengths[b];
    const int n = min((L + 63) >> 6, 8);
    const size_t mat = (size_t)S * S;

    float off = g_off2[(n - 1) * BB + b];
    smem_load_direct(g_buf2 + ((size_t)(n - 1) * BB + b) * mat, Asm);
    for (int k = n - 2; k >= 0; --k) {
        smem_load_trans(g_buf2 + ((size_t)k * BB + b) * mat, Btsm);
        off += g_off2[k * BB + b];
        __syncthreads();
        off += cta_gemm_rescale(Asm, Btsm, red);
    }
    __syncthreads();

    // sum of all entries of Asm
    int idx = threadIdx.x * 8;
    int r = idx >> 6, c0 = idx & 63;
    float s = 0.f;
#pragma unroll
    for (int q = 0; q < 8; ++q) s += __bfloat162float(Asm[r * LDA + c0 + q]);
#pragma unroll
    for (int o = 16; o; o >>= 1) s += __shfl_xor_sync(0xffffffffu, s, o);
    const int w = threadIdx.x >> 5, lane = threadIdx.x & 31;
    if (lane == 0) red[w] = s;
    __syncthreads();
    if (threadIdx.x == 0) {
        float tot = red[0];
#pragma unroll
        for (int i = 1; i < 16; ++i) tot += red[i];
        double vt = ((double)log2f(tot) + (double)off) * 0.6931471805599453094;
        out[b] = (float)vt;
    }
}

extern "C" void kernel_launch(void* const* d_in, const int* in_sizes, int n_in,
                              void* d_out, int out_size)
{
    const float* theta   = (const float*)d_in[0];
    const int*   lengths = (const int*)d_in[1];
    float*       out     = (float*)d_out;

    passA<<<dim3(TT / 8, BB), 512>>>(theta, lengths);
    passB<<<dim3(TT / 64, BB), 512>>>(lengths);
    passC<<<BB, 512>>>(lengths, out);
}

// round 7
// speedup vs baseline: 3.4467x; 1.6737x over previous
#include <cuda_runtime.h>
#include <cuda_bf16.h>
#include <cstdint>

// PackedViterbi as a parallel matrix-product tree, TRANSPOSE-FREE data flow.
// We accumulate M = P^T = E_{t0}^T * E_{t0+1}^T * ... (ascending t), so that
// mma.row.col's col-major B operand of E^T is exactly a row-major-stored E tile
// (conflict-free direct stores + direct u32 fragment reads). The chunk-start
// A = E_{t0}^T comes from ldmatrix.x4.trans on the direct tile (conflict-free).
// Pass B/C combine row-major chunk products with ldmatrix.x2.trans B-fragments.
// Final Vt uses sum of ALL entries (transpose-invariant). Exact power-of-2
// rescale after each GEMM; offsets accumulated in fp32, applied at the end.
// Depth-1 register prefetch of next leaf theta hides LDG latency behind GEMM.

static constexpr int S   = 64;
static constexpr int TT  = 512;
static constexpr int BB  = 64;
static constexpr int LDA = 72;            // padded SMEM stride (bf16 elems)

__device__ __nv_bfloat16 g_buf1[64 * BB * S * S];  // chunk products M_c = P_c^T
__device__ float         g_off1[64 * BB];
__device__ __nv_bfloat16 g_buf2[8 * BB * S * S];   // super-chunk products
__device__ float         g_off2[8 * BB];

__device__ __forceinline__ float ex2f_(float x) {
    float y; asm("ex2.approx.ftz.f32 %0, %1;" : "=f"(y) : "f"(x)); return y;
}

__device__ __forceinline__ void mma16816(float c[4], const uint32_t a[4],
                                         uint32_t b0, uint32_t b1) {
    asm volatile(
        "mma.sync.aligned.m16n8k16.row.col.f32.bf16.bf16.f32 "
        "{%0,%1,%2,%3}, {%4,%5,%6,%7}, {%8,%9}, {%0,%1,%2,%3};\n"
        : "+f"(c[0]), "+f"(c[1]), "+f"(c[2]), "+f"(c[3])
        : "r"(a[0]), "r"(a[1]), "r"(a[2]), "r"(a[3]), "r"(b0), "r"(b1));
}
__device__ __forceinline__ void ldm_x4_t(uint32_t a[4], uint32_t addr) {
    asm volatile("ldmatrix.sync.aligned.m8n8.x4.trans.shared.b16 {%0,%1,%2,%3}, [%4];"
                 : "=r"(a[0]), "=r"(a[1]), "=r"(a[2]), "=r"(a[3]) : "r"(addr));
}
__device__ __forceinline__ void ldm_x2_t(uint32_t b[2], uint32_t addr) {
    asm volatile("ldmatrix.sync.aligned.m8n8.x2.trans.shared.b16 {%0,%1}, [%2];"
                 : "=r"(b[0]), "=r"(b[1]) : "r"(addr));
}

struct F8 { float4 a, b; };
__device__ __forceinline__ F8 ldg8(const float* __restrict__ p) {
    F8 r; const float4* q = (const float4*)p; r.a = q[0]; r.b = q[1]; return r;
}

// convert 8 thetas -> E' = 2^(theta*log2e - 16), store row-major (conflict-free)
__device__ __forceinline__ void conv_store(const F8& v, __nv_bfloat16* s) {
    const float L2E = 1.4426950408889634f;
    int idx = threadIdx.x * 8;
    int r = idx >> 6, c0 = idx & 63;
    float e[8];
    e[0] = ex2f_(fmaf(v.a.x, L2E, -16.f)); e[1] = ex2f_(fmaf(v.a.y, L2E, -16.f));
    e[2] = ex2f_(fmaf(v.a.z, L2E, -16.f)); e[3] = ex2f_(fmaf(v.a.w, L2E, -16.f));
    e[4] = ex2f_(fmaf(v.b.x, L2E, -16.f)); e[5] = ex2f_(fmaf(v.b.y, L2E, -16.f));
    e[6] = ex2f_(fmaf(v.b.z, L2E, -16.f)); e[7] = ex2f_(fmaf(v.b.w, L2E, -16.f));
    __nv_bfloat16 t[8];
#pragma unroll
    for (int q = 0; q < 8; ++q) t[q] = __float2bfloat16(e[q]);
    *(uint4*)(s + r * LDA + c0) = *(uint4*)t;
}

__device__ __forceinline__ void smem_put(const uint4& v, __nv_bfloat16* s) {
    int idx = threadIdx.x * 8;
    *(uint4*)(s + (idx >> 6) * LDA + (idx & 63)) = v;
}
__device__ __forceinline__ void smem_store(const __nv_bfloat16* s,
                                           __nv_bfloat16* __restrict__ g) {
    int idx = threadIdx.x * 8;
    *(uint4*)(g + idx) = *(const uint4*)(s + (idx >> 6) * LDA + (idx & 63));
}

// Asm <- rescale( Asm * Btsm_op ), everything row-major in SMEM.
// ATRANS: A-fragments = (Asm tile)^T via ldmatrix.x4.trans (chunk start).
// BLDM:   B = Btsm (col-major frag) via ldmatrix.x2.trans (pass B/C).
// !BLDM:  B = Btsm^T (col-major frag) via direct u32 reads (pass A leaves).
template <bool ATRANS, bool BLDM>
__device__ __forceinline__ float cta_gemm_rescale(__nv_bfloat16* Asm,
                                                  const __nv_bfloat16* Btsm,
                                                  float* red) {
    const int tid = threadIdx.x;
    const int w = tid >> 5, lane = tid & 31;
    const int g = lane >> 2, t4 = lane & 3;
    const int rb = (w >> 2) * 16;
    const int ng = (w & 3) * 2;

    uint32_t a[4][4];
    if (ATRANS) {
        const int mi = lane >> 3, r8 = lane & 7;
        const int colA = rb + ((mi & 1) ? 8 : 0);
        const int rowO = ((mi & 2) ? 8 : 0) + r8;
#pragma unroll
        for (int ks = 0; ks < 4; ++ks) {
            uint32_t ad = (uint32_t)__cvta_generic_to_shared(
                Asm + (ks * 16 + rowO) * LDA + colA);
            ldm_x4_t(a[ks], ad);
        }
    } else {
#pragma unroll
        for (int ks = 0; ks < 4; ++ks) {
            const __nv_bfloat16* base = Asm + (rb + g) * LDA + ks * 16 + t4 * 2;
            a[ks][0] = *(const uint32_t*)(base);
            a[ks][1] = *(const uint32_t*)(base + 8 * LDA);
            a[ks][2] = *(const uint32_t*)(base + 8);
            a[ks][3] = *(const uint32_t*)(base + 8 * LDA + 8);
        }
    }
    float c[2][4];
#pragma unroll
    for (int nt = 0; nt < 2; ++nt) {
        c[nt][0] = c[nt][1] = c[nt][2] = c[nt][3] = 0.f;
        const int n0 = (ng + nt) * 8;
#pragma unroll
        for (int ks = 0; ks < 4; ++ks) {
            uint32_t b0, b1;
            if (BLDM) {
                const int r8 = lane & 7, ti = (lane >> 3) & 1;
                uint32_t ad = (uint32_t)__cvta_generic_to_shared(
                    Btsm + (ks * 16 + ti * 8 + r8) * LDA + n0);
                uint32_t bb[2]; ldm_x2_t(bb, ad);
                b0 = bb[0]; b1 = bb[1];
            } else {
                const __nv_bfloat16* bb = Btsm + (n0 + g) * LDA + ks * 16 + t4 * 2;
                b0 = *(const uint32_t*)bb;
                b1 = *(const uint32_t*)(bb + 8);
            }
            mma16816(c[nt], a[ks], b0, b1);
        }
    }
    __syncthreads();                       // all reads of Asm/Btsm complete
    float m = 0.f;
#pragma unroll
    for (int nt = 0; nt < 2; ++nt)
#pragma unroll
        for (int q = 0; q < 4; ++q) m = fmaxf(m, c[nt][q]);
#pragma unroll
    for (int off = 16; off; off >>= 1)
        m = fmaxf(m, __shfl_xor_sync(0xffffffffu, m, off));
    if (lane == 0) red[w] = m;
    __syncthreads();
    if (tid == 0) {
        float mm = red[0];
#pragma unroll
        for (int i = 1; i < 16; ++i) mm = fmaxf(mm, red[i]);
        int sft = (int)((__float_as_uint(mm) >> 23) & 0xFF) - 126;   // mm*2^-s in [0.5,1)
        red[16] = __uint_as_float((uint32_t)(127 - sft) << 23);      // exact 2^-s
        red[17] = (float)sft;
    }
    __syncthreads();
    const float scale = red[16];
    const float shift = red[17];
#pragma unroll
    for (int nt = 0; nt < 2; ++nt) {
        int col = (ng + nt) * 8 + t4 * 2;
        __nv_bfloat162 lo = __floats2bfloat162_rn(c[nt][0] * scale, c[nt][1] * scale);
        __nv_bfloat162 hi = __floats2bfloat162_rn(c[nt][2] * scale, c[nt][3] * scale);
        *(uint32_t*)(Asm + (rb + g) * LDA + col)     = *(uint32_t*)&lo;
        *(uint32_t*)(Asm + (rb + g + 8) * LDA + col) = *(uint32_t*)&hi;
    }
    __syncthreads();                       // Asm updated before next use
    return shift;
}

// ---- Pass A: chunks of 8 timesteps, M_c = E_{t0}^T ... E_{thi-1}^T ----------
__global__ void __launch_bounds__(512, 2)
passA(const float* __restrict__ theta, const int* __restrict__ lengths) {
    __shared__ __nv_bfloat16 Asm[S * LDA];
    __shared__ __nv_bfloat16 Btsm[S * LDA];
    __shared__ float red[18];
    const int c = blockIdx.x, b = blockIdx.y;
    const int L = lengths[b];
    const int t0 = c * 8;
    if (L <= t0) return;
    const int thi = min(L, t0 + 8);
    const int idx = threadIdx.x * 8;
    const size_t mat = (size_t)S * S;
    const float* tbase = theta + (size_t)b * mat + idx;
    const size_t tstride = (size_t)BB * mat;

    F8 rA = ldg8(tbase + (size_t)t0 * tstride);
    float off = 16.f * (float)(thi - t0);

    if (thi == t0 + 1) {                   // single leaf: M = E^T
        conv_store(rA, Asm);
        __syncthreads();
        const int r = idx >> 6, c0 = idx & 63;
        __nv_bfloat16 t[8];
#pragma unroll
        for (int q = 0; q < 8; ++q) t[q] = Asm[(c0 + q) * LDA + r];
        *(uint4*)(g_buf1 + ((size_t)c * BB + b) * mat + idx) = *(uint4*)t;
        if (threadIdx.x == 0) g_off1[c * BB + b] = off;
        return;
    }

    F8 rN = ldg8(tbase + (size_t)(t0 + 1) * tstride);
    conv_store(rA, Asm);                   // E_{t0} direct
    // first GEMM (A = E_{t0}^T via ldmatrix.trans)
    conv_store(rN, Btsm);
    if (t0 + 2 < thi) rN = ldg8(tbase + (size_t)(t0 + 2) * tstride);
    __syncthreads();
    off += cta_gemm_rescale<true, false>(Asm, Btsm, red);
    for (int t = t0 + 2; t < thi; ++t) {
        conv_store(rN, Btsm);
        if (t + 1 < thi) rN = ldg8(tbase + (size_t)(t + 1) * tstride);
        __syncthreads();
        off += cta_gemm_rescale<false, false>(Asm, Btsm, red);
    }
    smem_store(Asm, g_buf1 + ((size_t)c * BB + b) * mat);
    if (threadIdx.x == 0) g_off1[c * BB + b] = off;
}

// ---- Pass B: combine 8 chunks ASCENDING: M_g = M_cb * M_cb+1 * ... ----------
__global__ void __launch_bounds__(512, 2)
passB(const int* __restrict__ lengths) {
    __shared__ __nv_bfloat16 Asm[S * LDA];
    __shared__ __nv_bfloat16 Btsm[S * LDA];
    __shared__ float red[18];
    const int cc = blockIdx.x, b = blockIdx.y;
    const int L = lengths[b];
    const int totalChunks = (L + 7) >> 3;
    const int nch = min(totalChunks - cc * 8, 8);
    if (nch <= 0) return;
    const int cb = cc * 8;
    const int idx = threadIdx.x * 8;
    const size_t mat = (size_t)S * S;

    float off = g_off1[cb * BB + b];
    smem_put(*(const uint4*)(g_buf1 + ((size_t)cb * BB + b) * mat + idx), Asm);
    uint4 rM;
    if (nch > 1) rM = *(const uint4*)(g_buf1 + ((size_t)(cb + 1) * BB + b) * mat + idx);
    for (int k = 1; k < nch; ++k) {
        smem_put(rM, Btsm);
        if (k + 1 < nch)
            rM = *(const uint4*)(g_buf1 + ((size_t)(cb + k + 1) * BB + b) * mat + idx);
        off += g_off1[(cb + k) * BB + b];
        __syncthreads();
        off += cta_gemm_rescale<false, true>(Asm, Btsm, red);
    }
    smem_store(Asm, g_buf2 + ((size_t)cc * BB + b) * mat);
    if (threadIdx.x == 0) g_off2[cc * BB + b] = off;
}

// ---- Pass C: combine super-chunks ASCENDING, then total-entry sum -----------
__global__ void __launch_bounds__(512, 1)
passC(const int* __restrict__ lengths, float* __restrict__ out) {
    __shared__ __nv_bfloat16 Asm[S * LDA];
    __shared__ __nv_bfloat16 Btsm[S * LDA];
    __shared__ float red[18];
    const int b = blockIdx.x;
    const int L = lengths[b];
    const int totalChunks = (L + 7) >> 3;
    const int n = (totalChunks + 7) >> 3;
    const int idx = threadIdx.x * 8;
    const size_t mat = (size_t)S * S;

    float off = g_off2[b];
    smem_put(*(const uint4*)(g_buf2 + (size_t)b * mat + idx), Asm);
    uint4 rM;
    if (n > 1) rM = *(const uint4*)(g_buf2 + ((size_t)BB + b) * mat + idx);
    for (int k = 1; k < n; ++k) {
        smem_put(rM, Btsm);
        if (k + 1 < n)
            rM = *(const uint4*)(g_buf2 + ((size_t)(k + 1) * BB + b) * mat + idx);
        off += g_off2[k * BB + b];
        __syncthreads();
        off += cta_gemm_rescale<false, true>(Asm, Btsm, red);
    }
    __syncthreads();

    // total sum of entries (transpose-invariant)
    const int r = idx >> 6, c0 = idx & 63;
    float s = 0.f;
#pragma unroll
    for (int q = 0; q < 8; ++q) s += __bfloat162float(Asm[r * LDA + c0 + q]);
#pragma unroll
    for (int o = 16; o; o >>= 1) s += __shfl_xor_sync(0xffffffffu, s, o);
    const int w = threadIdx.x >> 5, lane = threadIdx.x & 31;
    if (lane == 0) red[w] = s;
    __syncthreads();
    if (threadIdx.x == 0) {
        float tot = red[0];
#pragma unroll
        for (int i = 1; i < 16; ++i) tot += red[i];
        double vt = ((double)log2f(tot) + (double)off) * 0.6931471805599453094;
        out[b] = (float)vt;
    }
}

extern "C" void kernel_launch(void* const* d_in, const int* in_sizes, int n_in,
                              void* d_out, int out_size)
{
    const float* theta   = (const float*)d_in[0];
    const int*   lengths = (const int*)d_in[1];
    float*       out     = (float*)d_out;

    passA<<<dim3(TT / 8, BB), 512>>>(theta, lengths);
    passB<<<dim3(TT / 64, BB), 512>>>(lengths);
    passC<<<BB, 512>>>(lengths, out);
}

// round 8
// speedup vs baseline: 3.7860x; 1.0985x over previous
#include <cuda_runtime.h>
#include <cuda_bf16.h>
#include <cstdint>

// PackedViterbi as a parallel matrix-product tree (transpose-free data flow),
// now with FIXED power-of-2 per-GEMM scaling (exact in the offset; bf16's
// 8-bit exponent absorbs the bounded drift) and ping-pong A/B tiles:
// exactly ONE __syncthreads per GEMM, no per-GEMM max-reduction.
// Exact max-rescale happens once per CTA at the end, on the final C registers,
// which are written straight to global (no SMEM roundtrip).
//   passA: chunk c, seq b: M_c = E_{t0}^T ... E_{thi-1}^T (7 GEMMs, x2^9 fixed)
//   passB: combine 8 chunks ascending (x2^-4 fixed)
//   passC: combine super-chunks, final total-entry sum from C registers.

static constexpr int S   = 64;
static constexpr int TT  = 512;
static constexpr int BB  = 64;
static constexpr int LDA = 72;            // padded SMEM stride (bf16 elems)

__device__ __nv_bfloat16 g_buf1[64 * BB * S * S];
__device__ float         g_off1[64 * BB];
__device__ __nv_bfloat16 g_buf2[8 * BB * S * S];
__device__ float         g_off2[8 * BB];

__device__ __forceinline__ float ex2f_(float x) {
    float y; asm("ex2.approx.ftz.f32 %0, %1;" : "=f"(y) : "f"(x)); return y;
}
__device__ __forceinline__ void mma16816(float c[4], const uint32_t a[4],
                                         uint32_t b0, uint32_t b1) {
    asm volatile(
        "mma.sync.aligned.m16n8k16.row.col.f32.bf16.bf16.f32 "
        "{%0,%1,%2,%3}, {%4,%5,%6,%7}, {%8,%9}, {%0,%1,%2,%3};\n"
        : "+f"(c[0]), "+f"(c[1]), "+f"(c[2]), "+f"(c[3])
        : "r"(a[0]), "r"(a[1]), "r"(a[2]), "r"(a[3]), "r"(b0), "r"(b1));
}
__device__ __forceinline__ void ldm_x4_t(uint32_t a[4], uint32_t addr) {
    asm volatile("ldmatrix.sync.aligned.m8n8.x4.trans.shared.b16 {%0,%1,%2,%3}, [%4];"
                 : "=r"(a[0]), "=r"(a[1]), "=r"(a[2]), "=r"(a[3]) : "r"(addr));
}
__device__ __forceinline__ void ldm_x2_t(uint32_t b[2], uint32_t addr) {
    asm volatile("ldmatrix.sync.aligned.m8n8.x2.trans.shared.b16 {%0,%1}, [%2];"
                 : "=r"(b[0]), "=r"(b[1]) : "r"(addr));
}

struct F8 { float4 a, b; };
__device__ __forceinline__ F8 ldg8(const float* __restrict__ p) {
    F8 r; const float4* q = (const float4*)p; r.a = q[0]; r.b = q[1]; return r;
}
// 8 thetas -> E' = 2^(theta*log2e - 16), stored row-major (conflict-free)
__device__ __forceinline__ void conv_store(const F8& v, __nv_bfloat16* s) {
    const float L2E = 1.4426950408889634f;
    int idx = threadIdx.x * 8;
    float e[8];
    e[0] = ex2f_(fmaf(v.a.x, L2E, -16.f)); e[1] = ex2f_(fmaf(v.a.y, L2E, -16.f));
    e[2] = ex2f_(fmaf(v.a.z, L2E, -16.f)); e[3] = ex2f_(fmaf(v.a.w, L2E, -16.f));
    e[4] = ex2f_(fmaf(v.b.x, L2E, -16.f)); e[5] = ex2f_(fmaf(v.b.y, L2E, -16.f));
    e[6] = ex2f_(fmaf(v.b.z, L2E, -16.f)); e[7] = ex2f_(fmaf(v.b.w, L2E, -16.f));
    __nv_bfloat16 t[8];
#pragma unroll
    for (int q = 0; q < 8; ++q) t[q] = __float2bfloat16(e[q]);
    *(uint4*)(s + (idx >> 6) * LDA + (idx & 63)) = *(uint4*)t;
}
__device__ __forceinline__ void smem_put(const uint4& v, __nv_bfloat16* s) {
    int idx = threadIdx.x * 8;
    *(uint4*)(s + (idx >> 6) * LDA + (idx & 63)) = v;
}

// C = Asrc * op(Bsrc); no syncs inside. Fragments per R7 layout.
template <bool ATRANS, bool BLDM>
__device__ __forceinline__ void cta_compute(const __nv_bfloat16* Asm,
                                            const __nv_bfloat16* Btsm,
                                            float c[2][4]) {
    const int tid = threadIdx.x;
    const int w = tid >> 5, lane = tid & 31;
    const int g = lane >> 2, t4 = lane & 3;
    const int rb = (w >> 2) * 16;
    const int ng = (w & 3) * 2;

    uint32_t a[4][4];
    if (ATRANS) {
        const int mi = lane >> 3, r8 = lane & 7;
        const int colA = rb + ((mi & 1) ? 8 : 0);
        const int rowO = ((mi & 2) ? 8 : 0) + r8;
#pragma unroll
        for (int ks = 0; ks < 4; ++ks) {
            uint32_t ad = (uint32_t)__cvta_generic_to_shared(
                Asm + (ks * 16 + rowO) * LDA + colA);
            ldm_x4_t(a[ks], ad);
        }
    } else {
#pragma unroll
        for (int ks = 0; ks < 4; ++ks) {
            const __nv_bfloat16* base = Asm + (rb + g) * LDA + ks * 16 + t4 * 2;
            a[ks][0] = *(const uint32_t*)(base);
            a[ks][1] = *(const uint32_t*)(base + 8 * LDA);
            a[ks][2] = *(const uint32_t*)(base + 8);
            a[ks][3] = *(const uint32_t*)(base + 8 * LDA + 8);
        }
    }
#pragma unroll
    for (int nt = 0; nt < 2; ++nt) {
        c[nt][0] = c[nt][1] = c[nt][2] = c[nt][3] = 0.f;
        const int n0 = (ng + nt) * 8;
#pragma unroll
        for (int ks = 0; ks < 4; ++ks) {
            uint32_t b0, b1;
            if (BLDM) {
                const int r8 = lane & 7, ti = (lane >> 3) & 1;
                uint32_t ad = (uint32_t)__cvta_generic_to_shared(
                    Btsm + (ks * 16 + ti * 8 + r8) * LDA + n0);
                uint32_t bb[2]; ldm_x2_t(bb, ad);
                b0 = bb[0]; b1 = bb[1];
            } else {
                const __nv_bfloat16* bb = Btsm + (n0 + g) * LDA + ks * 16 + t4 * 2;
                b0 = *(const uint32_t*)bb;
                b1 = *(const uint32_t*)(bb + 8);
            }
            mma16816(c[nt], a[ks], b0, b1);
        }
    }
}

__device__ __forceinline__ void wb_smem(const float c[2][4], float scl,
                                        __nv_bfloat16* dst) {
    const int tid = threadIdx.x;
    const int w = tid >> 5, lane = tid & 31;
    const int g = lane >> 2, t4 = lane & 3;
    const int rb = (w >> 2) * 16;
    const int ng = (w & 3) * 2;
#pragma unroll
    for (int nt = 0; nt < 2; ++nt) {
        int col = (ng + nt) * 8 + t4 * 2;
        __nv_bfloat162 lo = __floats2bfloat162_rn(c[nt][0] * scl, c[nt][1] * scl);
        __nv_bfloat162 hi = __floats2bfloat162_rn(c[nt][2] * scl, c[nt][3] * scl);
        *(uint32_t*)(dst + (rb + g) * LDA + col)     = *(uint32_t*)&lo;
        *(uint32_t*)(dst + (rb + g + 8) * LDA + col) = *(uint32_t*)&hi;
    }
}
__device__ __forceinline__ void wb_global(const float c[2][4], float scl,
                                          __nv_bfloat16* __restrict__ dst) {
    const int tid = threadIdx.x;
    const int w = tid >> 5, lane = tid & 31;
    const int g = lane >> 2, t4 = lane & 3;
    const int rb = (w >> 2) * 16;
    const int ng = (w & 3) * 2;
#pragma unroll
    for (int nt = 0; nt < 2; ++nt) {
        int col = (ng + nt) * 8 + t4 * 2;
        __nv_bfloat162 lo = __floats2bfloat162_rn(c[nt][0] * scl, c[nt][1] * scl);
        __nv_bfloat162 hi = __floats2bfloat162_rn(c[nt][2] * scl, c[nt][3] * scl);
        *(uint32_t*)(dst + (rb + g) * S + col)     = *(uint32_t*)&lo;
        *(uint32_t*)(dst + (rb + g + 8) * S + col) = *(uint32_t*)&hi;
    }
}

// exact power-of-2 scale from final C regs: scale = 2^-sft, max*scale in [0.5,1)
__device__ __forceinline__ void exact_scale(const float c[2][4], float* red,
                                            float& scale, float& sft) {
    const int tid = threadIdx.x;
    const int w = tid >> 5, lane = tid & 31;
    float m = 0.f;
#pragma unroll
    for (int nt = 0; nt < 2; ++nt)
#pragma unroll
        for (int q = 0; q < 4; ++q) m = fmaxf(m, c[nt][q]);
#pragma unroll
    for (int o = 16; o; o >>= 1)
        m = fmaxf(m, __shfl_xor_sync(0xffffffffu, m, o));
    if (lane == 0) red[w] = m;
    __syncthreads();
    if (tid == 0) {
        float mm = red[0];
#pragma unroll
        for (int i = 1; i < 16; ++i) mm = fmaxf(mm, red[i]);
        int s = (int)((__float_as_uint(mm) >> 23) & 0xFF) - 126;
        red[16] = __uint_as_float((uint32_t)(127 - s) << 23);
        red[17] = (float)s;
    }
    __syncthreads();
    scale = red[16];
    sft   = red[17];
}

// ---- Pass A ------------------------------------------------------------------
__global__ void __launch_bounds__(512, 2)
passA(const float* __restrict__ theta, const int* __restrict__ lengths) {
    __shared__ __nv_bfloat16 Abuf[2][S * LDA];
    __shared__ __nv_bfloat16 Bbuf[2][S * LDA];
    __shared__ float red[20];
    const int c = blockIdx.x, b = blockIdx.y;
    const int L = lengths[b];
    const int t0 = c * 8;
    if (L <= t0) return;
    const int thi = min(L, t0 + 8);
    const int idx = threadIdx.x * 8;
    const size_t mat = (size_t)S * S;
    const float* tbase = theta + (size_t)b * mat + idx;
    const size_t tstride = (size_t)BB * mat;

    F8 rA = ldg8(tbase + (size_t)t0 * tstride);

    if (thi == t0 + 1) {                   // single leaf: M = E^T
        conv_store(rA, Abuf[0]);
        __syncthreads();
        const int r = idx >> 6, c0 = idx & 63;
        __nv_bfloat16 t[8];
#pragma unroll
        for (int q = 0; q < 8; ++q) t[q] = Abuf[0][(c0 + q) * LDA + r];
        *(uint4*)(g_buf1 + ((size_t)c * BB + b) * mat + idx) = *(uint4*)t;
        if (threadIdx.x == 0) g_off1[c * BB + b] = 16.f;
        return;
    }

    F8 rN = ldg8(tbase + (size_t)(t0 + 1) * tstride);
    conv_store(rA, Abuf[0]);
    conv_store(rN, Bbuf[0]);
    if (t0 + 2 < thi) rN = ldg8(tbase + (size_t)(t0 + 2) * tstride);
    __syncthreads();

    float c_[2][4];
    cta_compute<true, false>(Abuf[0], Bbuf[0], c_);   // GEMM 0

    const int ngemm = thi - t0 - 1;
    int pa = 0, pb = 0;
    for (int k = 1; k < ngemm; ++k) {
        conv_store(rN, Bbuf[pb ^ 1]);                 // leaf t0+k+1
        if (t0 + k + 2 < thi) rN = ldg8(tbase + (size_t)(t0 + k + 2) * tstride);
        wb_smem(c_, 512.f, Abuf[pa ^ 1]);             // fixed x2^9
        pa ^= 1; pb ^= 1;
        __syncthreads();
        cta_compute<false, false>(Abuf[pa], Bbuf[pb], c_);
    }

    float scale, sft;
    exact_scale(c_, red, scale, sft);
    wb_global(c_, scale, g_buf1 + ((size_t)c * BB + b) * mat);
    if (threadIdx.x == 0)
        g_off1[c * BB + b] = 16.f * (float)(thi - t0) - 9.f * (float)(ngemm - 1) + sft;
}

// ---- Pass B ------------------------------------------------------------------
__global__ void __launch_bounds__(512, 2)
passB(const int* __restrict__ lengths) {
    __shared__ __nv_bfloat16 Abuf[2][S * LDA];
    __shared__ __nv_bfloat16 Bbuf[2][S * LDA];
    __shared__ float red[20];
    const int cc = blockIdx.x, b = blockIdx.y;
    const int L = lengths[b];
    const int totalChunks = (L + 7) >> 3;
    const int nch = min(totalChunks - cc * 8, 8);
    if (nch <= 0) return;
    const int cb = cc * 8;
    const int idx = threadIdx.x * 8;
    const size_t mat = (size_t)S * S;

    if (nch == 1) {                        // pass-through copy
        *(uint4*)(g_buf2 + ((size_t)cc * BB + b) * mat + idx) =
            *(const uint4*)(g_buf1 + ((size_t)cb * BB + b) * mat + idx);
        if (threadIdx.x == 0) g_off2[cc * BB + b] = g_off1[cb * BB + b];
        return;
    }

    float off = g_off1[cb * BB + b] + g_off1[(cb + 1) * BB + b];
    smem_put(*(const uint4*)(g_buf1 + ((size_t)cb * BB + b) * mat + idx), Abuf[0]);
    smem_put(*(const uint4*)(g_buf1 + ((size_t)(cb + 1) * BB + b) * mat + idx), Bbuf[0]);
    uint4 rM;
    if (nch > 2) rM = *(const uint4*)(g_buf1 + ((size_t)(cb + 2) * BB + b) * mat + idx);
    __syncthreads();

    float c_[2][4];
    cta_compute<false, true>(Abuf[0], Bbuf[0], c_);

    int pa = 0, pb = 0;
    for (int k = 2; k < nch; ++k) {
        smem_put(rM, Bbuf[pb ^ 1]);
        if (k + 1 < nch)
            rM = *(const uint4*)(g_buf1 + ((size_t)(cb + k + 1) * BB + b) * mat + idx);
        wb_smem(c_, 0.0625f, Abuf[pa ^ 1]);            // fixed x2^-4
        off += g_off1[(cb + k) * BB + b];
        pa ^= 1; pb ^= 1;
        __syncthreads();
        cta_compute<false, true>(Abuf[pa], Bbuf[pb], c_);
    }

    float scale, sft;
    exact_scale(c_, red, scale, sft);
    wb_global(c_, scale, g_buf2 + ((size_t)cc * BB + b) * mat);
    if (threadIdx.x == 0)
        g_off2[cc * BB + b] = off + 4.f * (float)(nch - 2) + sft;
}

// ---- Pass C ------------------------------------------------------------------
__global__ void __launch_bounds__(512, 1)
passC(const int* __restrict__ lengths, float* __restrict__ out) {
    __shared__ __nv_bfloat16 Abuf[2][S * LDA];
    __shared__ __nv_bfloat16 Bbuf[2][S * LDA];
    __shared__ float red[20];
    const int b = blockIdx.x;
    const int L = lengths[b];
    const int totalChunks = (L + 7) >> 3;
    const int n = (totalChunks + 7) >> 3;
    const int idx = threadIdx.x * 8;
    const int w = threadIdx.x >> 5, lane = threadIdx.x & 31;
    const size_t mat = (size_t)S * S;

    float s;
    float off;
    if (n == 1) {
        uint4 v = *(const uint4*)(g_buf2 + (size_t)b * mat + idx);
        const __nv_bfloat16* h = (const __nv_bfloat16*)&v;
        s = 0.f;
#pragma unroll
        for (int q = 0; q < 8; ++q) s += __bfloat162float(h[q]);
        off = g_off2[b];
    } else {
        off = g_off2[b] + g_off2[BB + b];
        smem_put(*(const uint4*)(g_buf2 + (size_t)b * mat + idx), Abuf[0]);
        smem_put(*(const uint4*)(g_buf2 + ((size_t)BB + b) * mat + idx), Bbuf[0]);
        uint4 rM;
        if (n > 2) rM = *(const uint4*)(g_buf2 + ((size_t)2 * BB + b) * mat + idx);
        __syncthreads();

        float c_[2][4];
        cta_compute<false, true>(Abuf[0], Bbuf[0], c_);
        int pa = 0, pb = 0;
        for (int k = 2; k < n; ++k) {
            smem_put(rM, Bbuf[pb ^ 1]);
            if (k + 1 < n)
                rM = *(const uint4*)(g_buf2 + ((size_t)(k + 1) * BB + b) * mat + idx);
            wb_smem(c_, 0.0625f, Abuf[pa ^ 1]);
            off += g_off2[k * BB + b];
            pa ^= 1; pb ^= 1;
            __syncthreads();
            cta_compute<false, true>(Abuf[pa], Bbuf[pb], c_);
        }
        off += 4.f * (float)(n - 2);
        s = 0.f;
#pragma unroll
        for (int nt = 0; nt < 2; ++nt)
#pragma unroll
            for (int q = 0; q < 4; ++q) s += c_[nt][q];
    }

#pragma unroll
    for (int o = 16; o; o >>= 1) s += __shfl_xor_sync(0xffffffffu, s, o);
    if (lane == 0) red[w] = s;
    __syncthreads();
    if (threadIdx.x == 0) {
        float tot = red[0];
#pragma unroll
        for (int i = 1; i < 16; ++i) tot += red[i];
        double vt = ((double)log2f(tot) + (double)off) * 0.6931471805599453094;
        out[b] = (float)vt;
    }
}

extern "C" void kernel_launch(void* const* d_in, const int* in_sizes, int n_in,
                              void* d_out, int out_size)
{
    const float* theta   = (const float*)d_in[0];
    const int*   lengths = (const int*)d_in[1];
    float*       out     = (float*)d_out;

    passA<<<dim3(TT / 8, BB), 512>>>(theta, lengths);
    passB<<<dim3(TT / 64, BB), 512>>>(lengths);
    passC<<<BB, 512>>>(lengths, out);
}